// round 3
// baseline (speedup 1.0000x reference)
#include <cuda_runtime.h>
#include <cuda_bf16.h>
#include <math.h>

// ---------------- constants ----------------
#define BATCH 2
#define LTOK 4096          // tokens per batch (16*16*16)
#define DIM 256
#define DEPTH 4
#define NST 16             // D_STATE
#define DTR 16             // DT_RANK
#define TC 64              // scan chunk length
#define NCH 64             // chunks per sequence (TC*NCH = 4096)

// ---------------- scratch (static device memory; no allocs) ----------------
__device__ float g_h[BATCH*LTOK*DIM];        // residual stream
__device__ float g_u[BATCH*LTOK*DIM];        // LN output
__device__ float g_xz[BATCH*LTOK*2*DIM];     // in_proj output (x_in | z)
__device__ float g_xc[BATCH*LTOK*DIM];       // silu(conv(x_in))
__device__ float g_delta[BATCH*LTOK*DIM];
__device__ float g_Bm[BATCH*LTOK*NST];
__device__ float g_Cm[BATCH*LTOK*NST];
__device__ float g_y[BATCH*LTOK*DIM];
__device__ float g_patch[BATCH*LTOK*64];     // patchified input
__device__ float g_Q[BATCH*NCH*DIM*NST];     // per-chunk partial states
__device__ float g_sd[BATCH*NCH*DIM];        // per-chunk sum of delta
__device__ float g_hs[BATCH*NCH*DIM*NST];    // per-chunk start states

// ---------------- patchify: x(2,64,64,64) -> (B*L, 64) ----------------
__global__ void patchify_kernel(const float* __restrict__ x) {
    int i = blockIdx.x * 256 + threadIdx.x;          // B*L*64 total
    int p = i & 63;
    int t = (i >> 6) & (LTOK - 1);
    int b = i >> 18;
    int pd = p & 3, pw = (p >> 2) & 3, ph = p >> 4;
    int di = t & 15, wi = (t >> 4) & 15, hi = t >> 8;
    int xi = ((b * 64 + hi * 4 + ph) * 64 + (wi * 4 + pw)) * 64 + (di * 4 + pd);
    g_patch[i] = x[xi];
}

// ---------------- SGEMM: C[M,N] = A[M,K] @ op(W) (+bias)(+res) ----------------
// wNK=1: W is (N,K) row-major (out = A @ W^T). wNK=0: W is (K,N) row-major.
#define TM 128
#define TN 64
#define TKK 16
__global__ __launch_bounds__(256) void sgemm_kernel(
    const float* __restrict__ A, const float* __restrict__ W,
    float* __restrict__ C, const float* __restrict__ bias,
    const float* __restrict__ res, int M, int N, int K, int wNK)
{
    __shared__ float As[TKK][TM + 4];
    __shared__ float Ws[TKK][TN + 4];
    int tid = threadIdx.x;
    int m0 = blockIdx.y * TM;
    int n0 = blockIdx.x * TN;
    int tx = tid & 15;       // n micro-tile: tx*4
    int ty = tid >> 4;       // m micro-tile: ty*8
    int lk = tid & 15;
    int lm = tid >> 4;
    int ln2 = tid & 63;
    int lk2 = tid >> 6;
    float acc[8][4];
    #pragma unroll
    for (int i = 0; i < 8; i++)
        #pragma unroll
        for (int j = 0; j < 4; j++) acc[i][j] = 0.f;

    for (int k0 = 0; k0 < K; k0 += TKK) {
        #pragma unroll
        for (int j = 0; j < 8; j++) {
            int m = lm + j * 16;
            As[lk][m] = A[(size_t)(m0 + m) * K + k0 + lk];
        }
        if (wNK) {
            #pragma unroll
            for (int j = 0; j < 4; j++) {
                int n = lm + j * 16;
                Ws[lk][n] = W[(size_t)(n0 + n) * K + k0 + lk];
            }
        } else {
            #pragma unroll
            for (int j = 0; j < 4; j++) {
                int k = lk2 + j * 4;
                Ws[k][ln2] = W[(size_t)(k0 + k) * N + n0 + ln2];
            }
        }
        __syncthreads();
        #pragma unroll
        for (int kk = 0; kk < TKK; kk++) {
            float a[8], bb[4];
            #pragma unroll
            for (int i = 0; i < 8; i++) a[i] = As[kk][ty * 8 + i];
            #pragma unroll
            for (int j = 0; j < 4; j++) bb[j] = Ws[kk][tx * 4 + j];
            #pragma unroll
            for (int i = 0; i < 8; i++)
                #pragma unroll
                for (int j = 0; j < 4; j++)
                    acc[i][j] = fmaf(a[i], bb[j], acc[i][j]);
        }
        __syncthreads();
    }
    #pragma unroll
    for (int i = 0; i < 8; i++) {
        int m = m0 + ty * 8 + i;
        #pragma unroll
        for (int j = 0; j < 4; j++) {
            int n = n0 + tx * 4 + j;
            float v = acc[i][j];
            if (bias) v += bias[n];
            if (res)  v += res[(size_t)m * N + n];
            C[(size_t)m * N + n] = v;
        }
    }
}

// ---------------- positional embedding (+patch bias) added to g_h ----------------
__global__ void pos_kernel(const float* __restrict__ rr, const float* __restrict__ ar,
                           const float* __restrict__ vr, const unsigned char* __restrict__ hv,
                           const float* __restrict__ patch_b)
{
    int bt = blockIdx.x;
    int b = bt >> 12;
    int t = bt & (LTOK - 1);
    int e = threadIdx.x;
    int hi = t >> 8, wi = (t >> 4) & 15, di = t & 15;
    float r = rr[b], a = ar[b], v = vr[b];
    // robust bool decode (works for 1-byte bool or int32 storage, true values)
    bool hasv = (hv[b] | hv[b * 4]) != 0;

    float c0raw = (float)hi * r;
    float mn0 = fminf(0.f, 15.f * r), mx0 = fmaxf(0.f, 15.f * r);
    float c1raw = ((float)wi - 8.f) * a;
    float mn1 = fminf(-8.f * a, 7.f * a), mx1 = fmaxf(-8.f * a, 7.f * a);
    float c2raw, mn2, mx2;
    if (hasv) {
        c2raw = ((float)di - 8.f) * v;
        mn2 = fminf(-8.f * v, 7.f * v); mx2 = fmaxf(-8.f * v, 7.f * v);
    } else {
        c2raw = (float)di * v;
        mn2 = fminf(0.f, 15.f * v); mx2 = fmaxf(0.f, 15.f * v);
    }
    float rg0 = mx0 - mn0; rg0 = (rg0 > 0.f) ? rg0 : 1.f;
    float rg1 = mx1 - mn1; rg1 = (rg1 > 0.f) ? rg1 : 1.f;
    float rg2 = mx2 - mn2; rg2 = (rg2 > 0.f) ? rg2 : 1.f;
    float c0 = (c0raw - mn0) / rg0;
    float c1 = (c1raw - mn1) / rg1;
    float c2 = (c2raw - mn2) / rg2;

    const float LN1E4 = 9.210340371976184f; // ln(10000)
    float pe;
    if (e < 86) {
        float c = c0;
        if (e < 43) {
            float om = __expf(-LN1E4 * (float)e / 43.f);
            pe = sinf(c * om);
        } else {
            float om = __expf(-LN1E4 * (float)(e - 43) / 43.f);
            pe = cosf(c * om);
        }
    } else if (e < 171) {
        int u = e - 86; float c = c1;
        if (u < 42)      pe = sinf(c * __expf(-LN1E4 * (float)u / 42.f));
        else if (u < 84) pe = cosf(c * __expf(-LN1E4 * (float)(u - 42) / 42.f));
        else             pe = c * 0.01f;
    } else {
        int u = e - 171; float c = c2;
        if (u < 42)      pe = sinf(c * __expf(-LN1E4 * (float)u / 42.f));
        else if (u < 84) pe = cosf(c * __expf(-LN1E4 * (float)(u - 42) / 42.f));
        else             pe = c * 0.01f;
    }
    g_h[(size_t)bt * DIM + e] += pe + patch_b[e];
}

// ---------------- layernorm (block per token, 256 threads) ----------------
__global__ void ln_kernel(const float* __restrict__ in, const float* __restrict__ w,
                          const float* __restrict__ b, float* __restrict__ out)
{
    int t = blockIdx.x;
    int d = threadIdx.x;
    int lane = d & 31, warp = d >> 5;
    __shared__ float red[8];
    __shared__ float s_mu, s_rstd;
    float v = in[(size_t)t * DIM + d];
    float s = v;
    #pragma unroll
    for (int off = 16; off; off >>= 1) s += __shfl_xor_sync(~0u, s, off);
    if (lane == 0) red[warp] = s;
    __syncthreads();
    if (d == 0) {
        float tot = 0.f;
        #pragma unroll
        for (int i = 0; i < 8; i++) tot += red[i];
        s_mu = tot * (1.f / DIM);
    }
    __syncthreads();
    float mu = s_mu;
    float diff = v - mu;
    float sq = diff * diff;
    #pragma unroll
    for (int off = 16; off; off >>= 1) sq += __shfl_xor_sync(~0u, sq, off);
    if (lane == 0) red[warp] = sq;
    __syncthreads();
    if (d == 0) {
        float tot = 0.f;
        #pragma unroll
        for (int i = 0; i < 8; i++) tot += red[i];
        s_rstd = rsqrtf(tot * (1.f / DIM) + 1e-5f);
    }
    __syncthreads();
    out[(size_t)t * DIM + d] = diff * s_rstd * w[d] + b[d];
}

// ---------------- prep: conv+silu, x_dbl, delta, B, C ----------------
__global__ void prep_kernel(const float* __restrict__ conv_w, const float* __restrict__ conv_b,
                            const float* __restrict__ xproj_w,
                            const float* __restrict__ dtw, const float* __restrict__ dtb)
{
    int bt = blockIdx.x;
    int b = bt >> 12;
    int t = bt & (LTOK - 1);
    int d = threadIdx.x;
    __shared__ float sxc[DIM];
    __shared__ float sdbl[48];

    float acc = conv_b[d];
    #pragma unroll
    for (int k = 0; k < 4; k++) {
        int tt = t - 3 + k;
        if (tt >= 0)
            acc = fmaf(conv_w[d * 4 + k], g_xz[((size_t)(b * LTOK + tt)) * 512 + d], acc);
    }
    float xcv = acc * (1.f / (1.f + __expf(-acc)));
    g_xc[(size_t)bt * DIM + d] = xcv;
    sxc[d] = xcv;
    __syncthreads();

    int warp = d >> 5, lane = d & 31;
    #pragma unroll
    for (int i = 0; i < 6; i++) {
        int o = warp * 6 + i;
        float s = 0.f;
        #pragma unroll
        for (int r = 0; r < 8; r++)
            s = fmaf(sxc[r * 32 + lane], xproj_w[o * 256 + r * 32 + lane], s);
        #pragma unroll
        for (int off = 16; off; off >>= 1) s += __shfl_xor_sync(~0u, s, off);
        if (lane == 0) sdbl[o] = s;
    }
    __syncthreads();

    float s = dtb[d];
    #pragma unroll
    for (int r = 0; r < 16; r++) s = fmaf(sdbl[r], dtw[d * 16 + r], s);
    float dl = (s > 20.f) ? s : log1pf(__expf(s));
    g_delta[(size_t)bt * DIM + d] = dl;
    if (d < 16)      g_Bm[(size_t)bt * NST + d]        = sdbl[16 + d];
    else if (d < 32) g_Cm[(size_t)bt * NST + (d - 16)] = sdbl[32 + (d - 16)];
}

// ---------------- scan pass1: per-chunk partial state + sum(delta) ----------------
__global__ void scan1_kernel(const float* __restrict__ A_log)
{
    int bc = blockIdx.x;            // b*NCH + c
    int b = bc >> 6;
    int c = bc & (NCH - 1);
    int d = threadIdx.x;
    __shared__ float sB[TC * NST];
    const float* Bg = g_Bm + (size_t)(b * LTOK + c * TC) * NST;
    for (int i = d; i < TC * NST; i += 256) sB[i] = Bg[i];
    __syncthreads();

    float A[NST], h[NST];
    #pragma unroll
    for (int n = 0; n < NST; n++) { A[n] = -__expf(A_log[d * NST + n]); h[n] = 0.f; }
    float sd = 0.f;
    size_t base = (size_t)(b * LTOK + c * TC) * DIM + d;
    for (int t = 0; t < TC; t++) {
        float dl  = g_delta[base + (size_t)t * DIM];
        float xcv = g_xc[base + (size_t)t * DIM];
        float dbx = dl * xcv;
        sd += dl;
        #pragma unroll
        for (int n = 0; n < NST; n++) {
            float da = __expf(dl * A[n]);
            h[n] = fmaf(da, h[n], dbx * sB[t * NST + n]);
        }
    }
    size_t q = ((size_t)bc * DIM + d) * NST;
    #pragma unroll
    for (int n = 0; n < NST; n++) g_Q[q + n] = h[n];
    g_sd[(size_t)bc * DIM + d] = sd;
}

// ---------------- scan pass2: sequential combine over chunks ----------------
__global__ void scan2_kernel(const float* __restrict__ A_log)
{
    int i = blockIdx.x * 256 + threadIdx.x;      // BATCH*DIM*NST = 8192
    int n = i & (NST - 1);
    int d = (i >> 4) & (DIM - 1);
    int b = i >> 12;
    float A = -__expf(A_log[d * NST + n]);
    float h = 0.f;
    for (int c = 0; c < NCH; c++) {
        size_t idx = (size_t)(b * NCH + c) * DIM + d;
        g_hs[idx * NST + n] = h;
        h = fmaf(__expf(A * g_sd[idx]), h, g_Q[idx * NST + n]);
    }
}

// ---------------- scan pass3: recompute within chunk + fused epilogue ----------------
__global__ void scan3_kernel(const float* __restrict__ A_log, const float* __restrict__ Dskip)
{
    int bc = blockIdx.x;
    int b = bc >> 6;
    int c = bc & (NCH - 1);
    int d = threadIdx.x;
    __shared__ float sB[TC * NST];
    __shared__ float sC[TC * NST];
    const float* Bg = g_Bm + (size_t)(b * LTOK + c * TC) * NST;
    const float* Cg = g_Cm + (size_t)(b * LTOK + c * TC) * NST;
    for (int i = d; i < TC * NST; i += 256) { sB[i] = Bg[i]; sC[i] = Cg[i]; }
    __syncthreads();

    float A[NST], h[NST];
    size_t hsb = ((size_t)bc * DIM + d) * NST;
    #pragma unroll
    for (int n = 0; n < NST; n++) {
        A[n] = -__expf(A_log[d * NST + n]);
        h[n] = g_hs[hsb + n];
    }
    float Dsk = Dskip[d];
    size_t base  = (size_t)(b * LTOK + c * TC) * DIM + d;
    size_t zbase = (size_t)(b * LTOK + c * TC) * 512 + 256 + d;
    for (int t = 0; t < TC; t++) {
        float dl  = g_delta[base + (size_t)t * DIM];
        float xcv = g_xc[base + (size_t)t * DIM];
        float dbx = dl * xcv;
        float y = 0.f;
        #pragma unroll
        for (int n = 0; n < NST; n++) {
            float da = __expf(dl * A[n]);
            h[n] = fmaf(da, h[n], dbx * sB[t * NST + n]);
            y = fmaf(h[n], sC[t * NST + n], y);
        }
        float z = g_xz[zbase + (size_t)t * 512];
        float sz = z * (1.f / (1.f + __expf(-z)));
        g_y[base + (size_t)t * DIM] = (y + xcv * Dsk) * sz;
    }
}

// ---------------- launch ----------------
extern "C" void kernel_launch(void* const* d_in, const int* in_sizes, int n_in,
                              void* d_out, int out_size)
{
    const float* x         = (const float*)d_in[0];
    const float* range_res = (const float*)d_in[1];
    const float* angle_res = (const float*)d_in[2];
    const float* vel_res   = (const float*)d_in[3];
    const unsigned char* hv= (const unsigned char*)d_in[4];
    const float* patch_w   = (const float*)d_in[5];
    const float* patch_b   = (const float*)d_in[6];
    const float* ln_w      = (const float*)d_in[7];
    const float* ln_b      = (const float*)d_in[8];
    const float* in_proj_w = (const float*)d_in[9];
    const float* conv_w    = (const float*)d_in[10];
    const float* conv_b    = (const float*)d_in[11];
    const float* xproj_w   = (const float*)d_in[12];
    const float* dtproj_w  = (const float*)d_in[13];
    const float* dtproj_b  = (const float*)d_in[14];
    const float* A_log     = (const float*)d_in[15];
    const float* D_skip    = (const float*)d_in[16];
    const float* outproj_w = (const float*)d_in[17];
    const float* normf_w   = (const float*)d_in[18];
    const float* normf_b   = (const float*)d_in[19];
    float* out = (float*)d_out;

    const int M = BATCH * LTOK;  // 8192

    float *p_h, *p_u, *p_xz, *p_y, *p_patch;
    cudaGetSymbolAddress((void**)&p_h, g_h);
    cudaGetSymbolAddress((void**)&p_u, g_u);
    cudaGetSymbolAddress((void**)&p_xz, g_xz);
    cudaGetSymbolAddress((void**)&p_y, g_y);
    cudaGetSymbolAddress((void**)&p_patch, g_patch);

    // 1) patchify + patch embed GEMM + pos embed
    patchify_kernel<<<(M * 64) / 256, 256>>>(x);
    {
        dim3 grid(DIM / TN, M / TM);
        sgemm_kernel<<<grid, 256>>>(p_patch, patch_w, p_h, nullptr, nullptr,
                                    M, DIM, 64, /*wNK=*/0);
    }
    pos_kernel<<<M, DIM>>>(range_res, angle_res, vel_res, hv, patch_b);

    // 2) mamba layers
    for (int l = 0; l < DEPTH; l++) {
        ln_kernel<<<M, DIM>>>(p_h, ln_w + l * DIM, ln_b + l * DIM, p_u);
        {
            dim3 grid((2 * DIM) / TN, M / TM);
            sgemm_kernel<<<grid, 256>>>(p_u, in_proj_w + (size_t)l * 2 * DIM * DIM,
                                        p_xz, nullptr, nullptr,
                                        M, 2 * DIM, DIM, /*wNK=*/1);
        }
        prep_kernel<<<M, DIM>>>(conv_w + l * DIM * 4, conv_b + l * DIM,
                                xproj_w + (size_t)l * 48 * DIM,
                                dtproj_w + (size_t)l * DIM * DTR,
                                dtproj_b + l * DIM);
        scan1_kernel<<<BATCH * NCH, DIM>>>(A_log + (size_t)l * DIM * NST);
        scan2_kernel<<<(BATCH * DIM * NST) / 256, 256>>>(A_log + (size_t)l * DIM * NST);
        scan3_kernel<<<BATCH * NCH, DIM>>>(A_log + (size_t)l * DIM * NST, D_skip + l * DIM);
        {
            dim3 grid(DIM / TN, M / TM);
            sgemm_kernel<<<grid, 256>>>(p_y, outproj_w + (size_t)l * DIM * DIM,
                                        p_h, nullptr, p_h,
                                        M, DIM, DIM, /*wNK=*/1);
        }
    }

    // 3) final layernorm -> output
    ln_kernel<<<M, DIM>>>(p_h, normf_w, normf_b, out);
}

// round 4
// speedup vs baseline: 1.0039x; 1.0039x over previous
#include <cuda_runtime.h>
#include <cuda_bf16.h>
#include <math.h>

// ---------------- constants ----------------
#define BATCH 2
#define LTOK 4096          // tokens per batch (16*16*16)
#define DIM 256
#define DEPTH 4
#define NST 16             // D_STATE
#define DTR 16             // DT_RANK
#define TC 64              // scan chunk length
#define NCH 64             // chunks per sequence (TC*NCH = 4096)

// ---------------- scratch (static device memory; no allocs) ----------------
__device__ float g_h[BATCH*LTOK*DIM];        // residual stream
__device__ float g_u[BATCH*LTOK*DIM];        // LN output
__device__ float g_xz[BATCH*LTOK*2*DIM];     // in_proj output (x_in | z)
__device__ float g_xc[BATCH*LTOK*DIM];       // silu(conv(x_in))
__device__ float g_delta[BATCH*LTOK*DIM];
__device__ float g_Bm[BATCH*LTOK*NST];
__device__ float g_Cm[BATCH*LTOK*NST];
__device__ float g_y[BATCH*LTOK*DIM];
__device__ float g_patch[BATCH*LTOK*64];     // patchified input
__device__ float g_Q[BATCH*NCH*DIM*NST];     // per-chunk partial states
__device__ float g_sd[BATCH*NCH*DIM];        // per-chunk sum of delta
__device__ float g_hs[BATCH*NCH*DIM*NST];    // per-chunk start states

// ---------------- patchify: x(2,64,64,64) -> (B*L, 64) ----------------
__global__ void patchify_kernel(const float* __restrict__ x) {
    int i = blockIdx.x * 256 + threadIdx.x;          // B*L*64 total
    int p = i & 63;
    int t = (i >> 6) & (LTOK - 1);
    int b = i >> 18;
    int pd = p & 3, pw = (p >> 2) & 3, ph = p >> 4;
    int di = t & 15, wi = (t >> 4) & 15, hi = t >> 8;
    int xi = ((b * 64 + hi * 4 + ph) * 64 + (wi * 4 + pw)) * 64 + (di * 4 + pd);
    g_patch[i] = x[xi];
}

// ---------------- SGEMM: C[M,N] = A[M,K] @ op(W) (+bias)(+res) ----------------
// wNK=1: W is (N,K) row-major (out = A @ W^T). wNK=0: W is (K,N) row-major.
#define TM 128
#define TN 64
#define TKK 16
__global__ __launch_bounds__(256) void sgemm_kernel(
    const float* __restrict__ A, const float* __restrict__ W,
    float* __restrict__ C, const float* __restrict__ bias,
    const float* __restrict__ res, int M, int N, int K, int wNK)
{
    __shared__ float As[TKK][TM + 4];
    __shared__ float Ws[TKK][TN + 4];
    int tid = threadIdx.x;
    int m0 = blockIdx.y * TM;
    int n0 = blockIdx.x * TN;
    int tx = tid & 15;       // n micro-tile: tx*4
    int ty = tid >> 4;       // m micro-tile: ty*8
    int lk = tid & 15;
    int lm = tid >> 4;
    int ln2 = tid & 63;
    int lk2 = tid >> 6;
    float acc[8][4];
    #pragma unroll
    for (int i = 0; i < 8; i++)
        #pragma unroll
        for (int j = 0; j < 4; j++) acc[i][j] = 0.f;

    for (int k0 = 0; k0 < K; k0 += TKK) {
        #pragma unroll
        for (int j = 0; j < 8; j++) {
            int m = lm + j * 16;
            As[lk][m] = A[(size_t)(m0 + m) * K + k0 + lk];
        }
        if (wNK) {
            #pragma unroll
            for (int j = 0; j < 4; j++) {
                int n = lm + j * 16;
                Ws[lk][n] = W[(size_t)(n0 + n) * K + k0 + lk];
            }
        } else {
            #pragma unroll
            for (int j = 0; j < 4; j++) {
                int k = lk2 + j * 4;
                Ws[k][ln2] = W[(size_t)(k0 + k) * N + n0 + ln2];
            }
        }
        __syncthreads();
        #pragma unroll
        for (int kk = 0; kk < TKK; kk++) {
            float a[8], bb[4];
            #pragma unroll
            for (int i = 0; i < 8; i++) a[i] = As[kk][ty * 8 + i];
            #pragma unroll
            for (int j = 0; j < 4; j++) bb[j] = Ws[kk][tx * 4 + j];
            #pragma unroll
            for (int i = 0; i < 8; i++)
                #pragma unroll
                for (int j = 0; j < 4; j++)
                    acc[i][j] = fmaf(a[i], bb[j], acc[i][j]);
        }
        __syncthreads();
    }
    #pragma unroll
    for (int i = 0; i < 8; i++) {
        int m = m0 + ty * 8 + i;
        #pragma unroll
        for (int j = 0; j < 4; j++) {
            int n = n0 + tx * 4 + j;
            float v = acc[i][j];
            if (bias) v += bias[n];
            if (res)  v += res[(size_t)m * N + n];
            C[(size_t)m * N + n] = v;
        }
    }
}

// ---------------- positional embedding (+patch bias) added to g_h ----------------
__global__ void pos_kernel(const float* __restrict__ rr, const float* __restrict__ ar,
                           const float* __restrict__ vr, const unsigned char* __restrict__ hv,
                           const float* __restrict__ patch_b)
{
    int bt = blockIdx.x;
    int b = bt >> 12;
    int t = bt & (LTOK - 1);
    int e = threadIdx.x;
    int hi = t >> 8, wi = (t >> 4) & 15, di = t & 15;
    float r = rr[b], a = ar[b], v = vr[b];
    // robust bool decode (works for 1-byte bool or int32 storage, true values)
    bool hasv = (hv[b] | hv[b * 4]) != 0;

    float c0raw = (float)hi * r;
    float mn0 = fminf(0.f, 15.f * r), mx0 = fmaxf(0.f, 15.f * r);
    float c1raw = ((float)wi - 8.f) * a;
    float mn1 = fminf(-8.f * a, 7.f * a), mx1 = fmaxf(-8.f * a, 7.f * a);
    float c2raw, mn2, mx2;
    if (hasv) {
        c2raw = ((float)di - 8.f) * v;
        mn2 = fminf(-8.f * v, 7.f * v); mx2 = fmaxf(-8.f * v, 7.f * v);
    } else {
        c2raw = (float)di * v;
        mn2 = fminf(0.f, 15.f * v); mx2 = fmaxf(0.f, 15.f * v);
    }
    float rg0 = mx0 - mn0; rg0 = (rg0 > 0.f) ? rg0 : 1.f;
    float rg1 = mx1 - mn1; rg1 = (rg1 > 0.f) ? rg1 : 1.f;
    float rg2 = mx2 - mn2; rg2 = (rg2 > 0.f) ? rg2 : 1.f;
    float c0 = (c0raw - mn0) / rg0;
    float c1 = (c1raw - mn1) / rg1;
    float c2 = (c2raw - mn2) / rg2;

    const float LN1E4 = 9.210340371976184f; // ln(10000)
    float pe;
    if (e < 86) {
        float c = c0;
        if (e < 43) {
            float om = __expf(-LN1E4 * (float)e / 43.f);
            pe = sinf(c * om);
        } else {
            float om = __expf(-LN1E4 * (float)(e - 43) / 43.f);
            pe = cosf(c * om);
        }
    } else if (e < 171) {
        int u = e - 86; float c = c1;
        if (u < 42)      pe = sinf(c * __expf(-LN1E4 * (float)u / 42.f));
        else if (u < 84) pe = cosf(c * __expf(-LN1E4 * (float)(u - 42) / 42.f));
        else             pe = c * 0.01f;
    } else {
        int u = e - 171; float c = c2;
        if (u < 42)      pe = sinf(c * __expf(-LN1E4 * (float)u / 42.f));
        else if (u < 84) pe = cosf(c * __expf(-LN1E4 * (float)(u - 42) / 42.f));
        else             pe = c * 0.01f;
    }
    g_h[(size_t)bt * DIM + e] += pe + patch_b[e];
}

// ---------------- layernorm (block per token, 256 threads) ----------------
__global__ void ln_kernel(const float* __restrict__ in, const float* __restrict__ w,
                          const float* __restrict__ b, float* __restrict__ out)
{
    int t = blockIdx.x;
    int d = threadIdx.x;
    int lane = d & 31, warp = d >> 5;
    __shared__ float red[8];
    __shared__ float s_mu, s_rstd;
    float v = in[(size_t)t * DIM + d];
    float s = v;
    #pragma unroll
    for (int off = 16; off; off >>= 1) s += __shfl_xor_sync(~0u, s, off);
    if (lane == 0) red[warp] = s;
    __syncthreads();
    if (d == 0) {
        float tot = 0.f;
        #pragma unroll
        for (int i = 0; i < 8; i++) tot += red[i];
        s_mu = tot * (1.f / DIM);
    }
    __syncthreads();
    float mu = s_mu;
    float diff = v - mu;
    float sq = diff * diff;
    #pragma unroll
    for (int off = 16; off; off >>= 1) sq += __shfl_xor_sync(~0u, sq, off);
    if (lane == 0) red[warp] = sq;
    __syncthreads();
    if (d == 0) {
        float tot = 0.f;
        #pragma unroll
        for (int i = 0; i < 8; i++) tot += red[i];
        s_rstd = rsqrtf(tot * (1.f / DIM) + 1e-5f);
    }
    __syncthreads();
    out[(size_t)t * DIM + d] = diff * s_rstd * w[d] + b[d];
}

// ---------------- prep: conv+silu, x_dbl, delta, B, C ----------------
__global__ void prep_kernel(const float* __restrict__ conv_w, const float* __restrict__ conv_b,
                            const float* __restrict__ xproj_w,
                            const float* __restrict__ dtw, const float* __restrict__ dtb)
{
    int bt = blockIdx.x;
    int b = bt >> 12;
    int t = bt & (LTOK - 1);
    int d = threadIdx.x;
    __shared__ float sxc[DIM];
    __shared__ float sdbl[48];

    float acc = conv_b[d];
    #pragma unroll
    for (int k = 0; k < 4; k++) {
        int tt = t - 3 + k;
        if (tt >= 0)
            acc = fmaf(conv_w[d * 4 + k], g_xz[((size_t)(b * LTOK + tt)) * 512 + d], acc);
    }
    float xcv = acc * (1.f / (1.f + __expf(-acc)));
    g_xc[(size_t)bt * DIM + d] = xcv;
    sxc[d] = xcv;
    __syncthreads();

    int warp = d >> 5, lane = d & 31;
    #pragma unroll
    for (int i = 0; i < 6; i++) {
        int o = warp * 6 + i;
        float s = 0.f;
        #pragma unroll
        for (int r = 0; r < 8; r++)
            s = fmaf(sxc[r * 32 + lane], xproj_w[o * 256 + r * 32 + lane], s);
        #pragma unroll
        for (int off = 16; off; off >>= 1) s += __shfl_xor_sync(~0u, s, off);
        if (lane == 0) sdbl[o] = s;
    }
    __syncthreads();

    float s = dtb[d];
    #pragma unroll
    for (int r = 0; r < 16; r++) s = fmaf(sdbl[r], dtw[d * 16 + r], s);
    float dl = (s > 20.f) ? s : log1pf(__expf(s));
    g_delta[(size_t)bt * DIM + d] = dl;
    if (d < 16)      g_Bm[(size_t)bt * NST + d]        = sdbl[16 + d];
    else if (d < 32) g_Cm[(size_t)bt * NST + (d - 16)] = sdbl[32 + (d - 16)];
}

// ---------------- scan pass1: per-chunk partial state + sum(delta) ----------------
__global__ void scan1_kernel(const float* __restrict__ A_log)
{
    int bc = blockIdx.x;            // b*NCH + c
    int b = bc >> 6;
    int c = bc & (NCH - 1);
    int d = threadIdx.x;
    __shared__ float sB[TC * NST];
    const float* Bg = g_Bm + (size_t)(b * LTOK + c * TC) * NST;
    for (int i = d; i < TC * NST; i += 256) sB[i] = Bg[i];
    __syncthreads();

    float A[NST], h[NST];
    #pragma unroll
    for (int n = 0; n < NST; n++) { A[n] = -__expf(A_log[d * NST + n]); h[n] = 0.f; }
    float sd = 0.f;
    size_t base = (size_t)(b * LTOK + c * TC) * DIM + d;
    for (int t = 0; t < TC; t++) {
        float dl  = g_delta[base + (size_t)t * DIM];
        float xcv = g_xc[base + (size_t)t * DIM];
        float dbx = dl * xcv;
        sd += dl;
        #pragma unroll
        for (int n = 0; n < NST; n++) {
            float da = __expf(dl * A[n]);
            h[n] = fmaf(da, h[n], dbx * sB[t * NST + n]);
        }
    }
    size_t q = ((size_t)bc * DIM + d) * NST;
    #pragma unroll
    for (int n = 0; n < NST; n++) g_Q[q + n] = h[n];
    g_sd[(size_t)bc * DIM + d] = sd;
}

// ---------------- scan pass2: sequential combine over chunks ----------------
__global__ void scan2_kernel(const float* __restrict__ A_log)
{
    int i = blockIdx.x * 256 + threadIdx.x;      // BATCH*DIM*NST = 8192
    int n = i & (NST - 1);
    int d = (i >> 4) & (DIM - 1);
    int b = i >> 12;
    float A = -__expf(A_log[d * NST + n]);
    float h = 0.f;
    for (int c = 0; c < NCH; c++) {
        size_t idx = (size_t)(b * NCH + c) * DIM + d;
        g_hs[idx * NST + n] = h;
        h = fmaf(__expf(A * g_sd[idx]), h, g_Q[idx * NST + n]);
    }
}

// ---------------- scan pass3: recompute within chunk + fused epilogue ----------------
__global__ void scan3_kernel(const float* __restrict__ A_log, const float* __restrict__ Dskip)
{
    int bc = blockIdx.x;
    int b = bc >> 6;
    int c = bc & (NCH - 1);
    int d = threadIdx.x;
    __shared__ float sB[TC * NST];
    __shared__ float sC[TC * NST];
    const float* Bg = g_Bm + (size_t)(b * LTOK + c * TC) * NST;
    const float* Cg = g_Cm + (size_t)(b * LTOK + c * TC) * NST;
    for (int i = d; i < TC * NST; i += 256) { sB[i] = Bg[i]; sC[i] = Cg[i]; }
    __syncthreads();

    float A[NST], h[NST];
    size_t hsb = ((size_t)bc * DIM + d) * NST;
    #pragma unroll
    for (int n = 0; n < NST; n++) {
        A[n] = -__expf(A_log[d * NST + n]);
        h[n] = g_hs[hsb + n];
    }
    float Dsk = Dskip[d];
    size_t base  = (size_t)(b * LTOK + c * TC) * DIM + d;
    size_t zbase = (size_t)(b * LTOK + c * TC) * 512 + 256 + d;
    for (int t = 0; t < TC; t++) {
        float dl  = g_delta[base + (size_t)t * DIM];
        float xcv = g_xc[base + (size_t)t * DIM];
        float dbx = dl * xcv;
        float y = 0.f;
        #pragma unroll
        for (int n = 0; n < NST; n++) {
            float da = __expf(dl * A[n]);
            h[n] = fmaf(da, h[n], dbx * sB[t * NST + n]);
            y = fmaf(h[n], sC[t * NST + n], y);
        }
        float z = g_xz[zbase + (size_t)t * 512];
        float sz = z * (1.f / (1.f + __expf(-z)));
        g_y[base + (size_t)t * DIM] = (y + xcv * Dsk) * sz;
    }
}

// ---------------- launch ----------------
extern "C" void kernel_launch(void* const* d_in, const int* in_sizes, int n_in,
                              void* d_out, int out_size)
{
    const float* x         = (const float*)d_in[0];
    const float* range_res = (const float*)d_in[1];
    const float* angle_res = (const float*)d_in[2];
    const float* vel_res   = (const float*)d_in[3];
    const unsigned char* hv= (const unsigned char*)d_in[4];
    const float* patch_w   = (const float*)d_in[5];
    const float* patch_b   = (const float*)d_in[6];
    const float* ln_w      = (const float*)d_in[7];
    const float* ln_b      = (const float*)d_in[8];
    const float* in_proj_w = (const float*)d_in[9];
    const float* conv_w    = (const float*)d_in[10];
    const float* conv_b    = (const float*)d_in[11];
    const float* xproj_w   = (const float*)d_in[12];
    const float* dtproj_w  = (const float*)d_in[13];
    const float* dtproj_b  = (const float*)d_in[14];
    const float* A_log     = (const float*)d_in[15];
    const float* D_skip    = (const float*)d_in[16];
    const float* outproj_w = (const float*)d_in[17];
    const float* normf_w   = (const float*)d_in[18];
    const float* normf_b   = (const float*)d_in[19];
    float* out = (float*)d_out;

    const int M = BATCH * LTOK;  // 8192

    float *p_h, *p_u, *p_xz, *p_y, *p_patch;
    cudaGetSymbolAddress((void**)&p_h, g_h);
    cudaGetSymbolAddress((void**)&p_u, g_u);
    cudaGetSymbolAddress((void**)&p_xz, g_xz);
    cudaGetSymbolAddress((void**)&p_y, g_y);
    cudaGetSymbolAddress((void**)&p_patch, g_patch);

    // 1) patchify + patch embed GEMM + pos embed
    patchify_kernel<<<(M * 64) / 256, 256>>>(x);
    {
        dim3 grid(DIM / TN, M / TM);
        sgemm_kernel<<<grid, 256>>>(p_patch, patch_w, p_h, nullptr, nullptr,
                                    M, DIM, 64, /*wNK=*/0);
    }
    pos_kernel<<<M, DIM>>>(range_res, angle_res, vel_res, hv, patch_b);

    // 2) mamba layers
    for (int l = 0; l < DEPTH; l++) {
        ln_kernel<<<M, DIM>>>(p_h, ln_w + l * DIM, ln_b + l * DIM, p_u);
        {
            dim3 grid((2 * DIM) / TN, M / TM);
            sgemm_kernel<<<grid, 256>>>(p_u, in_proj_w + (size_t)l * 2 * DIM * DIM,
                                        p_xz, nullptr, nullptr,
                                        M, 2 * DIM, DIM, /*wNK=*/1);
        }
        prep_kernel<<<M, DIM>>>(conv_w + l * DIM * 4, conv_b + l * DIM,
                                xproj_w + (size_t)l * 48 * DIM,
                                dtproj_w + (size_t)l * DIM * DTR,
                                dtproj_b + l * DIM);
        scan1_kernel<<<BATCH * NCH, DIM>>>(A_log + (size_t)l * DIM * NST);
        scan2_kernel<<<(BATCH * DIM * NST) / 256, 256>>>(A_log + (size_t)l * DIM * NST);
        scan3_kernel<<<BATCH * NCH, DIM>>>(A_log + (size_t)l * DIM * NST, D_skip + l * DIM);
        {
            dim3 grid(DIM / TN, M / TM);
            sgemm_kernel<<<grid, 256>>>(p_y, outproj_w + (size_t)l * DIM * DIM,
                                        p_h, nullptr, p_h,
                                        M, DIM, DIM, /*wNK=*/1);
        }
    }

    // 3) final layernorm -> output
    ln_kernel<<<M, DIM>>>(p_h, normf_w, normf_b, out);
}

// round 5
// speedup vs baseline: 1.1845x; 1.1799x over previous
#include <cuda_runtime.h>
#include <cuda_bf16.h>
#include <math.h>

// ---------------- constants ----------------
#define BATCH 2
#define LTOK 4096          // tokens per batch (16*16*16)
#define DIM 256
#define DEPTH 4
#define NST 16             // D_STATE
#define DTR 16             // DT_RANK
#define TC 64              // scan chunk length
#define NCH 64             // chunks per sequence (TC*NCH = 4096)

// ---------------- scratch (static device memory; no allocs) ----------------
__device__ float g_h[BATCH*LTOK*DIM];        // residual stream
__device__ float g_u[BATCH*LTOK*DIM];        // LN output
__device__ float g_xz[BATCH*LTOK*2*DIM];     // in_proj output (x_in | z)
__device__ float g_xc[BATCH*LTOK*DIM];       // silu(conv(x_in))
__device__ float g_delta[BATCH*LTOK*DIM];
__device__ float g_Bm[BATCH*LTOK*NST];
__device__ float g_Cm[BATCH*LTOK*NST];
__device__ float g_y[BATCH*LTOK*DIM];
__device__ float g_patch[BATCH*LTOK*64];     // patchified input
__device__ float g_Q[BATCH*NCH*DIM*NST];     // per-chunk partial states
__device__ float g_sd[BATCH*NCH*DIM];        // per-chunk sum of delta
__device__ float g_hs[BATCH*NCH*DIM*NST];    // per-chunk start states

// ---------------- patchify: x(2,64,64,64) -> (B*L, 64) ----------------
__global__ void patchify_kernel(const float* __restrict__ x) {
    int i = blockIdx.x * 256 + threadIdx.x;          // B*L*64 total
    int p = i & 63;
    int t = (i >> 6) & (LTOK - 1);
    int b = i >> 18;
    int pd = p & 3, pw = (p >> 2) & 3, ph = p >> 4;
    int di = t & 15, wi = (t >> 4) & 15, hi = t >> 8;
    int xi = ((b * 64 + hi * 4 + ph) * 64 + (wi * 4 + pw)) * 64 + (di * 4 + pd);
    g_patch[i] = x[xi];
}

// ---------------- tf32 helpers ----------------
__device__ __forceinline__ float2 tf32_split(float a) {
    unsigned h, l;
    asm("cvt.rna.tf32.f32 %0, %1;" : "=r"(h) : "f"(a));
    float hf = __uint_as_float(h);
    float lo = a - hf;
    asm("cvt.rna.tf32.f32 %0, %1;" : "=r"(l) : "f"(lo));
    return make_float2(hf, __uint_as_float(l));
}

__device__ __forceinline__ void mma_tf32(float* c, const unsigned* a, const unsigned* b) {
    asm volatile(
        "mma.sync.aligned.m16n8k8.row.col.f32.tf32.tf32.f32 "
        "{%0,%1,%2,%3}, {%4,%5,%6,%7}, {%8,%9}, {%0,%1,%2,%3};\n"
        : "+f"(c[0]), "+f"(c[1]), "+f"(c[2]), "+f"(c[3])
        : "r"(a[0]), "r"(a[1]), "r"(a[2]), "r"(a[3]), "r"(b[0]), "r"(b[1]));
}

// ---------------- tensor-core GEMM (3xTF32), C[M,N] = A[M,K] @ op(W) (+res) ----
// wNK=1: W is (N,K) row-major (out = A @ W^T). wNK=0: W is (K,N) row-major.
// Block tile 128x64x32, 8 warps (4x2), warp tile 32x32.
#define SSTR 36          // float2 stride; 36 mod 16 == 4 -> conflict-free frags
#define GEMM_SMEM ((128 + 64) * SSTR * (int)sizeof(float2))

__global__ __launch_bounds__(256) void gemm_tf32_kernel(
    const float* __restrict__ A, const float* __restrict__ W,
    float* __restrict__ C, const float* __restrict__ res,
    int M, int N, int K, int wNK)
{
    extern __shared__ float2 smem[];
    float2 (*sA)[SSTR] = (float2(*)[SSTR])smem;
    float2 (*sB)[SSTR] = (float2(*)[SSTR])(smem + 128 * SSTR);

    int tid = threadIdx.x;
    int lane = tid & 31;
    int warp = tid >> 5;
    int wm = warp & 3;           // 0..3 -> 32 rows each
    int wn = warp >> 2;          // 0..1 -> 32 cols each
    int m0 = blockIdx.y * 128;
    int n0 = blockIdx.x * 64;
    int lr = lane >> 2;          // 0..7
    int lc = lane & 3;           // 0..3

    float acc[2][4][4];
    #pragma unroll
    for (int i = 0; i < 2; i++)
        #pragma unroll
        for (int j = 0; j < 4; j++)
            #pragma unroll
            for (int q = 0; q < 4; q++) acc[i][j][q] = 0.f;

    float4 pA[4], pB[2];

    // prefetch first k-block
    {
        int k0 = 0;
        #pragma unroll
        for (int j = 0; j < 4; j++) {
            int lin = tid + j * 256;
            int row = lin >> 3, kq = (lin & 7) * 4;
            pA[j] = *(const float4*)(A + (size_t)(m0 + row) * K + k0 + kq);
        }
        if (wNK) {
            #pragma unroll
            for (int j = 0; j < 2; j++) {
                int lin = tid + j * 256;
                int n = lin >> 3, kq = (lin & 7) * 4;
                pB[j] = *(const float4*)(W + (size_t)(n0 + n) * K + k0 + kq);
            }
        } else {
            #pragma unroll
            for (int j = 0; j < 2; j++) {
                int lin = tid + j * 256;
                int kk = lin >> 4, n4 = (lin & 15) * 4;
                pB[j] = *(const float4*)(W + (size_t)(k0 + kk) * N + n0 + n4);
            }
        }
    }

    for (int k0 = 0; k0 < K; k0 += 32) {
        // store staged tile (split into hi/lo tf32 pairs)
        #pragma unroll
        for (int j = 0; j < 4; j++) {
            int lin = tid + j * 256;
            int row = lin >> 3, kq = (lin & 7) * 4;
            sA[row][kq + 0] = tf32_split(pA[j].x);
            sA[row][kq + 1] = tf32_split(pA[j].y);
            sA[row][kq + 2] = tf32_split(pA[j].z);
            sA[row][kq + 3] = tf32_split(pA[j].w);
        }
        if (wNK) {
            #pragma unroll
            for (int j = 0; j < 2; j++) {
                int lin = tid + j * 256;
                int n = lin >> 3, kq = (lin & 7) * 4;
                sB[n][kq + 0] = tf32_split(pB[j].x);
                sB[n][kq + 1] = tf32_split(pB[j].y);
                sB[n][kq + 2] = tf32_split(pB[j].z);
                sB[n][kq + 3] = tf32_split(pB[j].w);
            }
        } else {
            #pragma unroll
            for (int j = 0; j < 2; j++) {
                int lin = tid + j * 256;
                int kk = lin >> 4, n4 = (lin & 15) * 4;
                sB[n4 + 0][kk] = tf32_split(pB[j].x);
                sB[n4 + 1][kk] = tf32_split(pB[j].y);
                sB[n4 + 2][kk] = tf32_split(pB[j].z);
                sB[n4 + 3][kk] = tf32_split(pB[j].w);
            }
        }
        __syncthreads();

        // prefetch next k-block (overlaps with compute below)
        int kn = k0 + 32;
        if (kn < K) {
            #pragma unroll
            for (int j = 0; j < 4; j++) {
                int lin = tid + j * 256;
                int row = lin >> 3, kq = (lin & 7) * 4;
                pA[j] = *(const float4*)(A + (size_t)(m0 + row) * K + kn + kq);
            }
            if (wNK) {
                #pragma unroll
                for (int j = 0; j < 2; j++) {
                    int lin = tid + j * 256;
                    int n = lin >> 3, kq = (lin & 7) * 4;
                    pB[j] = *(const float4*)(W + (size_t)(n0 + n) * K + kn + kq);
                }
            } else {
                #pragma unroll
                for (int j = 0; j < 2; j++) {
                    int lin = tid + j * 256;
                    int kk = lin >> 4, n4 = (lin & 15) * 4;
                    pB[j] = *(const float4*)(W + (size_t)(kn + kk) * N + n0 + n4);
                }
            }
        }

        #pragma unroll
        for (int kk = 0; kk < 4; kk++) {
            int k8 = kk * 8;
            unsigned ah[2][4], al[2][4], bh[4][2], bl[4][2];
            #pragma unroll
            for (int mt = 0; mt < 2; mt++) {
                int r0 = wm * 32 + mt * 16 + lr;
                float2 x0 = sA[r0][k8 + lc];
                float2 x1 = sA[r0 + 8][k8 + lc];
                float2 x2 = sA[r0][k8 + lc + 4];
                float2 x3 = sA[r0 + 8][k8 + lc + 4];
                ah[mt][0] = __float_as_uint(x0.x); al[mt][0] = __float_as_uint(x0.y);
                ah[mt][1] = __float_as_uint(x1.x); al[mt][1] = __float_as_uint(x1.y);
                ah[mt][2] = __float_as_uint(x2.x); al[mt][2] = __float_as_uint(x2.y);
                ah[mt][3] = __float_as_uint(x3.x); al[mt][3] = __float_as_uint(x3.y);
            }
            #pragma unroll
            for (int nt = 0; nt < 4; nt++) {
                int nn = wn * 32 + nt * 8 + lr;
                float2 y0 = sB[nn][k8 + lc];
                float2 y1 = sB[nn][k8 + lc + 4];
                bh[nt][0] = __float_as_uint(y0.x); bl[nt][0] = __float_as_uint(y0.y);
                bh[nt][1] = __float_as_uint(y1.x); bl[nt][1] = __float_as_uint(y1.y);
            }
            #pragma unroll
            for (int mt = 0; mt < 2; mt++)
                #pragma unroll
                for (int nt = 0; nt < 4; nt++) {
                    mma_tf32(acc[mt][nt], ah[mt], bh[nt]);
                    mma_tf32(acc[mt][nt], al[mt], bh[nt]);
                    mma_tf32(acc[mt][nt], ah[mt], bl[nt]);
                }
        }
        __syncthreads();
    }

    // epilogue
    #pragma unroll
    for (int mt = 0; mt < 2; mt++) {
        int row = m0 + wm * 32 + mt * 16 + lr;
        #pragma unroll
        for (int nt = 0; nt < 4; nt++) {
            int col = n0 + wn * 32 + nt * 8 + lc * 2;
            float2 v0 = make_float2(acc[mt][nt][0], acc[mt][nt][1]);
            float2 v1 = make_float2(acc[mt][nt][2], acc[mt][nt][3]);
            if (res) {
                float2 r0 = *(const float2*)(res + (size_t)row * N + col);
                float2 r1 = *(const float2*)(res + (size_t)(row + 8) * N + col);
                v0.x += r0.x; v0.y += r0.y;
                v1.x += r1.x; v1.y += r1.y;
            }
            *(float2*)(C + (size_t)row * N + col) = v0;
            *(float2*)(C + (size_t)(row + 8) * N + col) = v1;
        }
    }
}

// ---------------- positional embedding (+patch bias) added to g_h ----------------
__global__ void pos_kernel(const float* __restrict__ rr, const float* __restrict__ ar,
                           const float* __restrict__ vr, const unsigned char* __restrict__ hv,
                           const float* __restrict__ patch_b)
{
    int bt = blockIdx.x;
    int b = bt >> 12;
    int t = bt & (LTOK - 1);
    int e = threadIdx.x;
    int hi = t >> 8, wi = (t >> 4) & 15, di = t & 15;
    float r = rr[b], a = ar[b], v = vr[b];
    bool hasv = (hv[b] | hv[b * 4]) != 0;

    float c0raw = (float)hi * r;
    float mn0 = fminf(0.f, 15.f * r), mx0 = fmaxf(0.f, 15.f * r);
    float c1raw = ((float)wi - 8.f) * a;
    float mn1 = fminf(-8.f * a, 7.f * a), mx1 = fmaxf(-8.f * a, 7.f * a);
    float c2raw, mn2, mx2;
    if (hasv) {
        c2raw = ((float)di - 8.f) * v;
        mn2 = fminf(-8.f * v, 7.f * v); mx2 = fmaxf(-8.f * v, 7.f * v);
    } else {
        c2raw = (float)di * v;
        mn2 = fminf(0.f, 15.f * v); mx2 = fmaxf(0.f, 15.f * v);
    }
    float rg0 = mx0 - mn0; rg0 = (rg0 > 0.f) ? rg0 : 1.f;
    float rg1 = mx1 - mn1; rg1 = (rg1 > 0.f) ? rg1 : 1.f;
    float rg2 = mx2 - mn2; rg2 = (rg2 > 0.f) ? rg2 : 1.f;
    float c0 = (c0raw - mn0) / rg0;
    float c1 = (c1raw - mn1) / rg1;
    float c2 = (c2raw - mn2) / rg2;

    const float LN1E4 = 9.210340371976184f; // ln(10000)
    float pe;
    if (e < 86) {
        float c = c0;
        if (e < 43) {
            float om = __expf(-LN1E4 * (float)e / 43.f);
            pe = sinf(c * om);
        } else {
            float om = __expf(-LN1E4 * (float)(e - 43) / 43.f);
            pe = cosf(c * om);
        }
    } else if (e < 171) {
        int u = e - 86; float c = c1;
        if (u < 42)      pe = sinf(c * __expf(-LN1E4 * (float)u / 42.f));
        else if (u < 84) pe = cosf(c * __expf(-LN1E4 * (float)(u - 42) / 42.f));
        else             pe = c * 0.01f;
    } else {
        int u = e - 171; float c = c2;
        if (u < 42)      pe = sinf(c * __expf(-LN1E4 * (float)u / 42.f));
        else if (u < 84) pe = cosf(c * __expf(-LN1E4 * (float)(u - 42) / 42.f));
        else             pe = c * 0.01f;
    }
    g_h[(size_t)bt * DIM + e] += pe + patch_b[e];
}

// ---------------- layernorm: warp per token, float4 vectorized ----------------
__global__ __launch_bounds__(256) void ln4_kernel(
    const float* __restrict__ in, const float* __restrict__ w,
    const float* __restrict__ b, float* __restrict__ out)
{
    int lane = threadIdx.x & 31;
    int warp = threadIdx.x >> 5;
    int t = blockIdx.x * 8 + warp;
    const float4* in4 = (const float4*)(in + (size_t)t * DIM);
    float4 v0 = in4[lane];
    float4 v1 = in4[lane + 32];
    float s = v0.x + v0.y + v0.z + v0.w + v1.x + v1.y + v1.z + v1.w;
    #pragma unroll
    for (int off = 16; off; off >>= 1) s += __shfl_xor_sync(~0u, s, off);
    float mu = s * (1.f / DIM);
    float d0x = v0.x - mu, d0y = v0.y - mu, d0z = v0.z - mu, d0w = v0.w - mu;
    float d1x = v1.x - mu, d1y = v1.y - mu, d1z = v1.z - mu, d1w = v1.w - mu;
    float q = d0x*d0x + d0y*d0y + d0z*d0z + d0w*d0w
            + d1x*d1x + d1y*d1y + d1z*d1z + d1w*d1w;
    #pragma unroll
    for (int off = 16; off; off >>= 1) q += __shfl_xor_sync(~0u, q, off);
    float rstd = rsqrtf(q * (1.f / DIM) + 1e-5f);
    float4 w0 = ((const float4*)w)[lane];
    float4 w1 = ((const float4*)w)[lane + 32];
    float4 b0 = ((const float4*)b)[lane];
    float4 b1 = ((const float4*)b)[lane + 32];
    float4 o0, o1;
    o0.x = d0x * rstd * w0.x + b0.x;  o0.y = d0y * rstd * w0.y + b0.y;
    o0.z = d0z * rstd * w0.z + b0.z;  o0.w = d0w * rstd * w0.w + b0.w;
    o1.x = d1x * rstd * w1.x + b1.x;  o1.y = d1y * rstd * w1.y + b1.y;
    o1.z = d1z * rstd * w1.z + b1.z;  o1.w = d1w * rstd * w1.w + b1.w;
    float4* out4 = (float4*)(out + (size_t)t * DIM);
    out4[lane] = o0;
    out4[lane + 32] = o1;
}

// ---------------- prep: conv+silu, x_dbl, delta, B, C ----------------
__global__ void prep_kernel(const float* __restrict__ conv_w, const float* __restrict__ conv_b,
                            const float* __restrict__ xproj_w,
                            const float* __restrict__ dtw, const float* __restrict__ dtb)
{
    int bt = blockIdx.x;
    int b = bt >> 12;
    int t = bt & (LTOK - 1);
    int d = threadIdx.x;
    __shared__ float sxc[DIM];
    __shared__ float sdbl[48];

    float acc = conv_b[d];
    #pragma unroll
    for (int k = 0; k < 4; k++) {
        int tt = t - 3 + k;
        if (tt >= 0)
            acc = fmaf(conv_w[d * 4 + k], g_xz[((size_t)(b * LTOK + tt)) * 512 + d], acc);
    }
    float xcv = acc * (1.f / (1.f + __expf(-acc)));
    g_xc[(size_t)bt * DIM + d] = xcv;
    sxc[d] = xcv;
    __syncthreads();

    int warp = d >> 5, lane = d & 31;
    #pragma unroll
    for (int i = 0; i < 6; i++) {
        int o = warp * 6 + i;
        float s = 0.f;
        #pragma unroll
        for (int r = 0; r < 8; r++)
            s = fmaf(sxc[r * 32 + lane], xproj_w[o * 256 + r * 32 + lane], s);
        #pragma unroll
        for (int off = 16; off; off >>= 1) s += __shfl_xor_sync(~0u, s, off);
        if (lane == 0) sdbl[o] = s;
    }
    __syncthreads();

    float s = dtb[d];
    #pragma unroll
    for (int r = 0; r < 16; r++) s = fmaf(sdbl[r], dtw[d * 16 + r], s);
    float dl = (s > 20.f) ? s : log1pf(__expf(s));
    g_delta[(size_t)bt * DIM + d] = dl;
    if (d < 16)      g_Bm[(size_t)bt * NST + d]        = sdbl[16 + d];
    else if (d < 32) g_Cm[(size_t)bt * NST + (d - 16)] = sdbl[32 + (d - 16)];
}

// ---------------- scan pass1: per-chunk partial state + sum(delta) ----------------
__global__ void scan1_kernel(const float* __restrict__ A_log)
{
    int bc = blockIdx.x;            // b*NCH + c
    int b = bc >> 6;
    int c = bc & (NCH - 1);
    int d = threadIdx.x;
    __shared__ float sB[TC * NST];
    const float* Bg = g_Bm + (size_t)(b * LTOK + c * TC) * NST;
    for (int i = d; i < TC * NST; i += 256) sB[i] = Bg[i];
    __syncthreads();

    float A[NST], h[NST];
    #pragma unroll
    for (int n = 0; n < NST; n++) { A[n] = -__expf(A_log[d * NST + n]); h[n] = 0.f; }
    float sd = 0.f;
    size_t base = (size_t)(b * LTOK + c * TC) * DIM + d;
    for (int t = 0; t < TC; t++) {
        float dl  = g_delta[base + (size_t)t * DIM];
        float xcv = g_xc[base + (size_t)t * DIM];
        float dbx = dl * xcv;
        sd += dl;
        #pragma unroll
        for (int n = 0; n < NST; n++) {
            float da = __expf(dl * A[n]);
            h[n] = fmaf(da, h[n], dbx * sB[t * NST + n]);
        }
    }
    size_t q = ((size_t)bc * DIM + d) * NST;
    #pragma unroll
    for (int n = 0; n < NST; n++) g_Q[q + n] = h[n];
    g_sd[(size_t)bc * DIM + d] = sd;
}

// ---------------- scan pass2: sequential combine over chunks ----------------
__global__ void scan2_kernel(const float* __restrict__ A_log)
{
    int i = blockIdx.x * 256 + threadIdx.x;      // BATCH*DIM*NST = 8192
    int n = i & (NST - 1);
    int d = (i >> 4) & (DIM - 1);
    int b = i >> 12;
    float A = -__expf(A_log[d * NST + n]);
    float h = 0.f;
    for (int c = 0; c < NCH; c++) {
        size_t idx = (size_t)(b * NCH + c) * DIM + d;
        g_hs[idx * NST + n] = h;
        h = fmaf(__expf(A * g_sd[idx]), h, g_Q[idx * NST + n]);
    }
}

// ---------------- scan pass3: recompute within chunk + fused epilogue ----------------
__global__ void scan3_kernel(const float* __restrict__ A_log, const float* __restrict__ Dskip)
{
    int bc = blockIdx.x;
    int b = bc >> 6;
    int c = bc & (NCH - 1);
    int d = threadIdx.x;
    __shared__ float sB[TC * NST];
    __shared__ float sC[TC * NST];
    const float* Bg = g_Bm + (size_t)(b * LTOK + c * TC) * NST;
    const float* Cg = g_Cm + (size_t)(b * LTOK + c * TC) * NST;
    for (int i = d; i < TC * NST; i += 256) { sB[i] = Bg[i]; sC[i] = Cg[i]; }
    __syncthreads();

    float A[NST], h[NST];
    size_t hsb = ((size_t)bc * DIM + d) * NST;
    #pragma unroll
    for (int n = 0; n < NST; n++) {
        A[n] = -__expf(A_log[d * NST + n]);
        h[n] = g_hs[hsb + n];
    }
    float Dsk = Dskip[d];
    size_t base  = (size_t)(b * LTOK + c * TC) * DIM + d;
    size_t zbase = (size_t)(b * LTOK + c * TC) * 512 + 256 + d;
    for (int t = 0; t < TC; t++) {
        float dl  = g_delta[base + (size_t)t * DIM];
        float xcv = g_xc[base + (size_t)t * DIM];
        float dbx = dl * xcv;
        float y = 0.f;
        #pragma unroll
        for (int n = 0; n < NST; n++) {
            float da = __expf(dl * A[n]);
            h[n] = fmaf(da, h[n], dbx * sB[t * NST + n]);
            y = fmaf(h[n], sC[t * NST + n], y);
        }
        float z = g_xz[zbase + (size_t)t * 512];
        float sz = z * (1.f / (1.f + __expf(-z)));
        g_y[base + (size_t)t * DIM] = (y + xcv * Dsk) * sz;
    }
}

// ---------------- launch ----------------
extern "C" void kernel_launch(void* const* d_in, const int* in_sizes, int n_in,
                              void* d_out, int out_size)
{
    const float* x         = (const float*)d_in[0];
    const float* range_res = (const float*)d_in[1];
    const float* angle_res = (const float*)d_in[2];
    const float* vel_res   = (const float*)d_in[3];
    const unsigned char* hv= (const unsigned char*)d_in[4];
    const float* patch_w   = (const float*)d_in[5];
    const float* patch_b   = (const float*)d_in[6];
    const float* ln_w      = (const float*)d_in[7];
    const float* ln_b      = (const float*)d_in[8];
    const float* in_proj_w = (const float*)d_in[9];
    const float* conv_w    = (const float*)d_in[10];
    const float* conv_b    = (const float*)d_in[11];
    const float* xproj_w   = (const float*)d_in[12];
    const float* dtproj_w  = (const float*)d_in[13];
    const float* dtproj_b  = (const float*)d_in[14];
    const float* A_log     = (const float*)d_in[15];
    const float* D_skip    = (const float*)d_in[16];
    const float* outproj_w = (const float*)d_in[17];
    const float* normf_w   = (const float*)d_in[18];
    const float* normf_b   = (const float*)d_in[19];
    float* out = (float*)d_out;

    const int M = BATCH * LTOK;  // 8192

    float *p_h, *p_u, *p_xz, *p_y, *p_patch;
    cudaGetSymbolAddress((void**)&p_h, g_h);
    cudaGetSymbolAddress((void**)&p_u, g_u);
    cudaGetSymbolAddress((void**)&p_xz, g_xz);
    cudaGetSymbolAddress((void**)&p_y, g_y);
    cudaGetSymbolAddress((void**)&p_patch, g_patch);

    cudaFuncSetAttribute(gemm_tf32_kernel,
                         cudaFuncAttributeMaxDynamicSharedMemorySize, GEMM_SMEM);

    // 1) patchify + patch embed GEMM + pos embed
    patchify_kernel<<<(M * 64) / 256, 256>>>(x);
    {
        dim3 grid(DIM / 64, M / 128);
        gemm_tf32_kernel<<<grid, 256, GEMM_SMEM>>>(p_patch, patch_w, p_h, nullptr,
                                                   M, DIM, 64, /*wNK=*/0);
    }
    pos_kernel<<<M, DIM>>>(range_res, angle_res, vel_res, hv, patch_b);

    // 2) mamba layers
    for (int l = 0; l < DEPTH; l++) {
        ln4_kernel<<<M / 8, 256>>>(p_h, ln_w + l * DIM, ln_b + l * DIM, p_u);
        {
            dim3 grid((2 * DIM) / 64, M / 128);
            gemm_tf32_kernel<<<grid, 256, GEMM_SMEM>>>(p_u, in_proj_w + (size_t)l * 2 * DIM * DIM,
                                                       p_xz, nullptr,
                                                       M, 2 * DIM, DIM, /*wNK=*/1);
        }
        prep_kernel<<<M, DIM>>>(conv_w + l * DIM * 4, conv_b + l * DIM,
                                xproj_w + (size_t)l * 48 * DIM,
                                dtproj_w + (size_t)l * DIM * DTR,
                                dtproj_b + l * DIM);
        scan1_kernel<<<BATCH * NCH, DIM>>>(A_log + (size_t)l * DIM * NST);
        scan2_kernel<<<(BATCH * DIM * NST) / 256, 256>>>(A_log + (size_t)l * DIM * NST);
        scan3_kernel<<<BATCH * NCH, DIM>>>(A_log + (size_t)l * DIM * NST, D_skip + l * DIM);
        {
            dim3 grid(DIM / 64, M / 128);
            gemm_tf32_kernel<<<grid, 256, GEMM_SMEM>>>(p_y, outproj_w + (size_t)l * DIM * DIM,
                                                       p_h, p_h,
                                                       M, DIM, DIM, /*wNK=*/1);
        }
    }

    // 3) final layernorm -> output
    ln4_kernel<<<M / 8, 256>>>(p_h, normf_w, normf_b, out);
}

// round 6
// speedup vs baseline: 1.1846x; 1.0001x over previous
#include <cuda_runtime.h>
#include <cuda_bf16.h>
#include <math.h>

// ---------------- constants ----------------
#define BATCH 2
#define LTOK 4096          // tokens per batch (16*16*16)
#define DIM 256
#define DEPTH 4
#define NST 16             // D_STATE
#define DTR 16             // DT_RANK
#define TC 64              // scan chunk length
#define NCH 64             // chunks per sequence (TC*NCH = 4096)

// ---------------- scratch (static device memory; no allocs) ----------------
__device__ float g_h[BATCH*LTOK*DIM];        // residual stream
__device__ float g_u[BATCH*LTOK*DIM];        // LN output
__device__ float g_xz[BATCH*LTOK*2*DIM];     // in_proj output (x_in | z)
__device__ float g_xc[BATCH*LTOK*DIM];       // silu(conv(x_in))
__device__ float g_delta[BATCH*LTOK*DIM];
__device__ float g_Bm[BATCH*LTOK*NST];
__device__ float g_Cm[BATCH*LTOK*NST];
__device__ float g_y[BATCH*LTOK*DIM];
__device__ float g_patch[BATCH*LTOK*64];     // patchified input
__device__ float g_Q[BATCH*NCH*DIM*NST];     // per-chunk partial states
__device__ float g_sd[BATCH*NCH*DIM];        // per-chunk sum of delta
__device__ float g_hs[BATCH*NCH*DIM*NST];    // per-chunk start states

// ---------------- patchify: x(2,64,64,64) -> (B*L, 64) ----------------
__global__ void patchify_kernel(const float* __restrict__ x) {
    int i = blockIdx.x * 256 + threadIdx.x;          // B*L*64 total
    int p = i & 63;
    int t = (i >> 6) & (LTOK - 1);
    int b = i >> 18;
    int pd = p & 3, pw = (p >> 2) & 3, ph = p >> 4;
    int di = t & 15, wi = (t >> 4) & 15, hi = t >> 8;
    int xi = ((b * 64 + hi * 4 + ph) * 64 + (wi * 4 + pw)) * 64 + (di * 4 + pd);
    g_patch[i] = x[xi];
}

// ---------------- tf32 helpers ----------------
__device__ __forceinline__ float2 tf32_split(float a) {
    unsigned h, l;
    asm("cvt.rna.tf32.f32 %0, %1;" : "=r"(h) : "f"(a));
    float hf = __uint_as_float(h);
    float lo = a - hf;
    asm("cvt.rna.tf32.f32 %0, %1;" : "=r"(l) : "f"(lo));
    return make_float2(hf, __uint_as_float(l));
}

__device__ __forceinline__ void mma_tf32(float* c, const unsigned* a, const unsigned* b) {
    asm volatile(
        "mma.sync.aligned.m16n8k8.row.col.f32.tf32.tf32.f32 "
        "{%0,%1,%2,%3}, {%4,%5,%6,%7}, {%8,%9}, {%0,%1,%2,%3};\n"
        : "+f"(c[0]), "+f"(c[1]), "+f"(c[2]), "+f"(c[3])
        : "r"(a[0]), "r"(a[1]), "r"(a[2]), "r"(a[3]), "r"(b[0]), "r"(b[1]));
}

// ---------------- tensor-core GEMM (3xTF32), C[M,N] = A[M,K] @ op(W) (+res) ----
// wNK=1: W is (N,K) row-major (out = A @ W^T). wNK=0: W is (K,N) row-major.
// Block tile 128x64x32, 8 warps (4x2), warp tile 32x32.
#define SSTR 36          // float2 stride; 36 mod 16 == 4 -> conflict-free frags
#define GEMM_SMEM ((128 + 64) * SSTR * (int)sizeof(float2))

__global__ __launch_bounds__(256) void gemm_tf32_kernel(
    const float* __restrict__ A, const float* __restrict__ W,
    float* __restrict__ C, const float* __restrict__ res,
    int M, int N, int K, int wNK)
{
    extern __shared__ float2 smem[];
    float2 (*sA)[SSTR] = (float2(*)[SSTR])smem;
    float2 (*sB)[SSTR] = (float2(*)[SSTR])(smem + 128 * SSTR);

    int tid = threadIdx.x;
    int lane = tid & 31;
    int warp = tid >> 5;
    int wm = warp & 3;           // 0..3 -> 32 rows each
    int wn = warp >> 2;          // 0..1 -> 32 cols each
    int m0 = blockIdx.y * 128;
    int n0 = blockIdx.x * 64;
    int lr = lane >> 2;          // 0..7
    int lc = lane & 3;           // 0..3

    float acc[2][4][4];
    #pragma unroll
    for (int i = 0; i < 2; i++)
        #pragma unroll
        for (int j = 0; j < 4; j++)
            #pragma unroll
            for (int q = 0; q < 4; q++) acc[i][j][q] = 0.f;

    float4 pA[4], pB[2];

    // prefetch first k-block
    {
        int k0 = 0;
        #pragma unroll
        for (int j = 0; j < 4; j++) {
            int lin = tid + j * 256;
            int row = lin >> 3, kq = (lin & 7) * 4;
            pA[j] = *(const float4*)(A + (size_t)(m0 + row) * K + k0 + kq);
        }
        if (wNK) {
            #pragma unroll
            for (int j = 0; j < 2; j++) {
                int lin = tid + j * 256;
                int n = lin >> 3, kq = (lin & 7) * 4;
                pB[j] = *(const float4*)(W + (size_t)(n0 + n) * K + k0 + kq);
            }
        } else {
            #pragma unroll
            for (int j = 0; j < 2; j++) {
                int lin = tid + j * 256;
                int kk = lin >> 4, n4 = (lin & 15) * 4;
                pB[j] = *(const float4*)(W + (size_t)(k0 + kk) * N + n0 + n4);
            }
        }
    }

    for (int k0 = 0; k0 < K; k0 += 32) {
        // store staged tile (split into hi/lo tf32 pairs)
        #pragma unroll
        for (int j = 0; j < 4; j++) {
            int lin = tid + j * 256;
            int row = lin >> 3, kq = (lin & 7) * 4;
            sA[row][kq + 0] = tf32_split(pA[j].x);
            sA[row][kq + 1] = tf32_split(pA[j].y);
            sA[row][kq + 2] = tf32_split(pA[j].z);
            sA[row][kq + 3] = tf32_split(pA[j].w);
        }
        if (wNK) {
            #pragma unroll
            for (int j = 0; j < 2; j++) {
                int lin = tid + j * 256;
                int n = lin >> 3, kq = (lin & 7) * 4;
                sB[n][kq + 0] = tf32_split(pB[j].x);
                sB[n][kq + 1] = tf32_split(pB[j].y);
                sB[n][kq + 2] = tf32_split(pB[j].z);
                sB[n][kq + 3] = tf32_split(pB[j].w);
            }
        } else {
            #pragma unroll
            for (int j = 0; j < 2; j++) {
                int lin = tid + j * 256;
                int kk = lin >> 4, n4 = (lin & 15) * 4;
                sB[n4 + 0][kk] = tf32_split(pB[j].x);
                sB[n4 + 1][kk] = tf32_split(pB[j].y);
                sB[n4 + 2][kk] = tf32_split(pB[j].z);
                sB[n4 + 3][kk] = tf32_split(pB[j].w);
            }
        }
        __syncthreads();

        // prefetch next k-block (overlaps with compute below)
        int kn = k0 + 32;
        if (kn < K) {
            #pragma unroll
            for (int j = 0; j < 4; j++) {
                int lin = tid + j * 256;
                int row = lin >> 3, kq = (lin & 7) * 4;
                pA[j] = *(const float4*)(A + (size_t)(m0 + row) * K + kn + kq);
            }
            if (wNK) {
                #pragma unroll
                for (int j = 0; j < 2; j++) {
                    int lin = tid + j * 256;
                    int n = lin >> 3, kq = (lin & 7) * 4;
                    pB[j] = *(const float4*)(W + (size_t)(n0 + n) * K + kn + kq);
                }
            } else {
                #pragma unroll
                for (int j = 0; j < 2; j++) {
                    int lin = tid + j * 256;
                    int kk = lin >> 4, n4 = (lin & 15) * 4;
                    pB[j] = *(const float4*)(W + (size_t)(kn + kk) * N + n0 + n4);
                }
            }
        }

        #pragma unroll
        for (int kk = 0; kk < 4; kk++) {
            int k8 = kk * 8;
            unsigned ah[2][4], al[2][4], bh[4][2], bl[4][2];
            #pragma unroll
            for (int mt = 0; mt < 2; mt++) {
                int r0 = wm * 32 + mt * 16 + lr;
                float2 x0 = sA[r0][k8 + lc];
                float2 x1 = sA[r0 + 8][k8 + lc];
                float2 x2 = sA[r0][k8 + lc + 4];
                float2 x3 = sA[r0 + 8][k8 + lc + 4];
                ah[mt][0] = __float_as_uint(x0.x); al[mt][0] = __float_as_uint(x0.y);
                ah[mt][1] = __float_as_uint(x1.x); al[mt][1] = __float_as_uint(x1.y);
                ah[mt][2] = __float_as_uint(x2.x); al[mt][2] = __float_as_uint(x2.y);
                ah[mt][3] = __float_as_uint(x3.x); al[mt][3] = __float_as_uint(x3.y);
            }
            #pragma unroll
            for (int nt = 0; nt < 4; nt++) {
                int nn = wn * 32 + nt * 8 + lr;
                float2 y0 = sB[nn][k8 + lc];
                float2 y1 = sB[nn][k8 + lc + 4];
                bh[nt][0] = __float_as_uint(y0.x); bl[nt][0] = __float_as_uint(y0.y);
                bh[nt][1] = __float_as_uint(y1.x); bl[nt][1] = __float_as_uint(y1.y);
            }
            #pragma unroll
            for (int mt = 0; mt < 2; mt++)
                #pragma unroll
                for (int nt = 0; nt < 4; nt++) {
                    mma_tf32(acc[mt][nt], ah[mt], bh[nt]);
                    mma_tf32(acc[mt][nt], al[mt], bh[nt]);
                    mma_tf32(acc[mt][nt], ah[mt], bl[nt]);
                }
        }
        __syncthreads();
    }

    // epilogue
    #pragma unroll
    for (int mt = 0; mt < 2; mt++) {
        int row = m0 + wm * 32 + mt * 16 + lr;
        #pragma unroll
        for (int nt = 0; nt < 4; nt++) {
            int col = n0 + wn * 32 + nt * 8 + lc * 2;
            float2 v0 = make_float2(acc[mt][nt][0], acc[mt][nt][1]);
            float2 v1 = make_float2(acc[mt][nt][2], acc[mt][nt][3]);
            if (res) {
                float2 r0 = *(const float2*)(res + (size_t)row * N + col);
                float2 r1 = *(const float2*)(res + (size_t)(row + 8) * N + col);
                v0.x += r0.x; v0.y += r0.y;
                v1.x += r1.x; v1.y += r1.y;
            }
            *(float2*)(C + (size_t)row * N + col) = v0;
            *(float2*)(C + (size_t)(row + 8) * N + col) = v1;
        }
    }
}

// ---------------- positional embedding (+patch bias) added to g_h ----------------
__global__ void pos_kernel(const float* __restrict__ rr, const float* __restrict__ ar,
                           const float* __restrict__ vr, const unsigned char* __restrict__ hv,
                           const float* __restrict__ patch_b)
{
    int bt = blockIdx.x;
    int b = bt >> 12;
    int t = bt & (LTOK - 1);
    int e = threadIdx.x;
    int hi = t >> 8, wi = (t >> 4) & 15, di = t & 15;
    float r = rr[b], a = ar[b], v = vr[b];
    bool hasv = (hv[b] | hv[b * 4]) != 0;

    float c0raw = (float)hi * r;
    float mn0 = fminf(0.f, 15.f * r), mx0 = fmaxf(0.f, 15.f * r);
    float c1raw = ((float)wi - 8.f) * a;
    float mn1 = fminf(-8.f * a, 7.f * a), mx1 = fmaxf(-8.f * a, 7.f * a);
    float c2raw, mn2, mx2;
    if (hasv) {
        c2raw = ((float)di - 8.f) * v;
        mn2 = fminf(-8.f * v, 7.f * v); mx2 = fmaxf(-8.f * v, 7.f * v);
    } else {
        c2raw = (float)di * v;
        mn2 = fminf(0.f, 15.f * v); mx2 = fmaxf(0.f, 15.f * v);
    }
    float rg0 = mx0 - mn0; rg0 = (rg0 > 0.f) ? rg0 : 1.f;
    float rg1 = mx1 - mn1; rg1 = (rg1 > 0.f) ? rg1 : 1.f;
    float rg2 = mx2 - mn2; rg2 = (rg2 > 0.f) ? rg2 : 1.f;
    float c0 = (c0raw - mn0) / rg0;
    float c1 = (c1raw - mn1) / rg1;
    float c2 = (c2raw - mn2) / rg2;

    const float LN1E4 = 9.210340371976184f; // ln(10000)
    float pe;
    if (e < 86) {
        float c = c0;
        if (e < 43) {
            float om = __expf(-LN1E4 * (float)e / 43.f);
            pe = sinf(c * om);
        } else {
            float om = __expf(-LN1E4 * (float)(e - 43) / 43.f);
            pe = cosf(c * om);
        }
    } else if (e < 171) {
        int u = e - 86; float c = c1;
        if (u < 42)      pe = sinf(c * __expf(-LN1E4 * (float)u / 42.f));
        else if (u < 84) pe = cosf(c * __expf(-LN1E4 * (float)(u - 42) / 42.f));
        else             pe = c * 0.01f;
    } else {
        int u = e - 171; float c = c2;
        if (u < 42)      pe = sinf(c * __expf(-LN1E4 * (float)u / 42.f));
        else if (u < 84) pe = cosf(c * __expf(-LN1E4 * (float)(u - 42) / 42.f));
        else             pe = c * 0.01f;
    }
    g_h[(size_t)bt * DIM + e] += pe + patch_b[e];
}

// ---------------- layernorm: warp per token, float4 vectorized ----------------
__global__ __launch_bounds__(256) void ln4_kernel(
    const float* __restrict__ in, const float* __restrict__ w,
    const float* __restrict__ b, float* __restrict__ out)
{
    int lane = threadIdx.x & 31;
    int warp = threadIdx.x >> 5;
    int t = blockIdx.x * 8 + warp;
    const float4* in4 = (const float4*)(in + (size_t)t * DIM);
    float4 v0 = in4[lane];
    float4 v1 = in4[lane + 32];
    float s = v0.x + v0.y + v0.z + v0.w + v1.x + v1.y + v1.z + v1.w;
    #pragma unroll
    for (int off = 16; off; off >>= 1) s += __shfl_xor_sync(~0u, s, off);
    float mu = s * (1.f / DIM);
    float d0x = v0.x - mu, d0y = v0.y - mu, d0z = v0.z - mu, d0w = v0.w - mu;
    float d1x = v1.x - mu, d1y = v1.y - mu, d1z = v1.z - mu, d1w = v1.w - mu;
    float q = d0x*d0x + d0y*d0y + d0z*d0z + d0w*d0w
            + d1x*d1x + d1y*d1y + d1z*d1z + d1w*d1w;
    #pragma unroll
    for (int off = 16; off; off >>= 1) q += __shfl_xor_sync(~0u, q, off);
    float rstd = rsqrtf(q * (1.f / DIM) + 1e-5f);
    float4 w0 = ((const float4*)w)[lane];
    float4 w1 = ((const float4*)w)[lane + 32];
    float4 b0 = ((const float4*)b)[lane];
    float4 b1 = ((const float4*)b)[lane + 32];
    float4 o0, o1;
    o0.x = d0x * rstd * w0.x + b0.x;  o0.y = d0y * rstd * w0.y + b0.y;
    o0.z = d0z * rstd * w0.z + b0.z;  o0.w = d0w * rstd * w0.w + b0.w;
    o1.x = d1x * rstd * w1.x + b1.x;  o1.y = d1y * rstd * w1.y + b1.y;
    o1.z = d1z * rstd * w1.z + b1.z;  o1.w = d1w * rstd * w1.w + b1.w;
    float4* out4 = (float4*)(out + (size_t)t * DIM);
    out4[lane] = o0;
    out4[lane + 32] = o1;
}

// ---------------- prep: conv+silu, x_dbl, delta, B, C ----------------
__global__ void prep_kernel(const float* __restrict__ conv_w, const float* __restrict__ conv_b,
                            const float* __restrict__ xproj_w,
                            const float* __restrict__ dtw, const float* __restrict__ dtb)
{
    int bt = blockIdx.x;
    int b = bt >> 12;
    int t = bt & (LTOK - 1);
    int d = threadIdx.x;
    __shared__ float sxc[DIM];
    __shared__ float sdbl[48];

    float acc = conv_b[d];
    #pragma unroll
    for (int k = 0; k < 4; k++) {
        int tt = t - 3 + k;
        if (tt >= 0)
            acc = fmaf(conv_w[d * 4 + k], g_xz[((size_t)(b * LTOK + tt)) * 512 + d], acc);
    }
    float xcv = acc * (1.f / (1.f + __expf(-acc)));
    g_xc[(size_t)bt * DIM + d] = xcv;
    sxc[d] = xcv;
    __syncthreads();

    int warp = d >> 5, lane = d & 31;
    #pragma unroll
    for (int i = 0; i < 6; i++) {
        int o = warp * 6 + i;
        float s = 0.f;
        #pragma unroll
        for (int r = 0; r < 8; r++)
            s = fmaf(sxc[r * 32 + lane], xproj_w[o * 256 + r * 32 + lane], s);
        #pragma unroll
        for (int off = 16; off; off >>= 1) s += __shfl_xor_sync(~0u, s, off);
        if (lane == 0) sdbl[o] = s;
    }
    __syncthreads();

    float s = dtb[d];
    #pragma unroll
    for (int r = 0; r < 16; r++) s = fmaf(sdbl[r], dtw[d * 16 + r], s);
    float dl = (s > 20.f) ? s : log1pf(__expf(s));
    g_delta[(size_t)bt * DIM + d] = dl;
    if (d < 16)      g_Bm[(size_t)bt * NST + d]        = sdbl[16 + d];
    else if (d < 32) g_Cm[(size_t)bt * NST + (d - 16)] = sdbl[32 + (d - 16)];
}

// ---------------- scan pass1: per-chunk partial state + sum(delta) ----------------
__global__ void scan1_kernel(const float* __restrict__ A_log)
{
    int bc = blockIdx.x;            // b*NCH + c
    int b = bc >> 6;
    int c = bc & (NCH - 1);
    int d = threadIdx.x;
    __shared__ float sB[TC * NST];
    const float* Bg = g_Bm + (size_t)(b * LTOK + c * TC) * NST;
    for (int i = d; i < TC * NST; i += 256) sB[i] = Bg[i];
    __syncthreads();

    float A[NST], h[NST];
    #pragma unroll
    for (int n = 0; n < NST; n++) { A[n] = -__expf(A_log[d * NST + n]); h[n] = 0.f; }
    float sd = 0.f;
    size_t base = (size_t)(b * LTOK + c * TC) * DIM + d;
    for (int t = 0; t < TC; t++) {
        float dl  = g_delta[base + (size_t)t * DIM];
        float xcv = g_xc[base + (size_t)t * DIM];
        float dbx = dl * xcv;
        sd += dl;
        #pragma unroll
        for (int n = 0; n < NST; n++) {
            float da = __expf(dl * A[n]);
            h[n] = fmaf(da, h[n], dbx * sB[t * NST + n]);
        }
    }
    size_t q = ((size_t)bc * DIM + d) * NST;
    #pragma unroll
    for (int n = 0; n < NST; n++) g_Q[q + n] = h[n];
    g_sd[(size_t)bc * DIM + d] = sd;
}

// ---------------- scan pass2: sequential combine over chunks ----------------
__global__ void scan2_kernel(const float* __restrict__ A_log)
{
    int i = blockIdx.x * 256 + threadIdx.x;      // BATCH*DIM*NST = 8192
    int n = i & (NST - 1);
    int d = (i >> 4) & (DIM - 1);
    int b = i >> 12;
    float A = -__expf(A_log[d * NST + n]);
    float h = 0.f;
    for (int c = 0; c < NCH; c++) {
        size_t idx = (size_t)(b * NCH + c) * DIM + d;
        g_hs[idx * NST + n] = h;
        h = fmaf(__expf(A * g_sd[idx]), h, g_Q[idx * NST + n]);
    }
}

// ---------------- scan pass3: recompute within chunk + fused epilogue ----------------
__global__ void scan3_kernel(const float* __restrict__ A_log, const float* __restrict__ Dskip)
{
    int bc = blockIdx.x;
    int b = bc >> 6;
    int c = bc & (NCH - 1);
    int d = threadIdx.x;
    __shared__ float sB[TC * NST];
    __shared__ float sC[TC * NST];
    const float* Bg = g_Bm + (size_t)(b * LTOK + c * TC) * NST;
    const float* Cg = g_Cm + (size_t)(b * LTOK + c * TC) * NST;
    for (int i = d; i < TC * NST; i += 256) { sB[i] = Bg[i]; sC[i] = Cg[i]; }
    __syncthreads();

    float A[NST], h[NST];
    size_t hsb = ((size_t)bc * DIM + d) * NST;
    #pragma unroll
    for (int n = 0; n < NST; n++) {
        A[n] = -__expf(A_log[d * NST + n]);
        h[n] = g_hs[hsb + n];
    }
    float Dsk = Dskip[d];
    size_t base  = (size_t)(b * LTOK + c * TC) * DIM + d;
    size_t zbase = (size_t)(b * LTOK + c * TC) * 512 + 256 + d;
    for (int t = 0; t < TC; t++) {
        float dl  = g_delta[base + (size_t)t * DIM];
        float xcv = g_xc[base + (size_t)t * DIM];
        float dbx = dl * xcv;
        float y = 0.f;
        #pragma unroll
        for (int n = 0; n < NST; n++) {
            float da = __expf(dl * A[n]);
            h[n] = fmaf(da, h[n], dbx * sB[t * NST + n]);
            y = fmaf(h[n], sC[t * NST + n], y);
        }
        float z = g_xz[zbase + (size_t)t * 512];
        float sz = z * (1.f / (1.f + __expf(-z)));
        g_y[base + (size_t)t * DIM] = (y + xcv * Dsk) * sz;
    }
}

// ---------------- launch ----------------
extern "C" void kernel_launch(void* const* d_in, const int* in_sizes, int n_in,
                              void* d_out, int out_size)
{
    const float* x         = (const float*)d_in[0];
    const float* range_res = (const float*)d_in[1];
    const float* angle_res = (const float*)d_in[2];
    const float* vel_res   = (const float*)d_in[3];
    const unsigned char* hv= (const unsigned char*)d_in[4];
    const float* patch_w   = (const float*)d_in[5];
    const float* patch_b   = (const float*)d_in[6];
    const float* ln_w      = (const float*)d_in[7];
    const float* ln_b      = (const float*)d_in[8];
    const float* in_proj_w = (const float*)d_in[9];
    const float* conv_w    = (const float*)d_in[10];
    const float* conv_b    = (const float*)d_in[11];
    const float* xproj_w   = (const float*)d_in[12];
    const float* dtproj_w  = (const float*)d_in[13];
    const float* dtproj_b  = (const float*)d_in[14];
    const float* A_log     = (const float*)d_in[15];
    const float* D_skip    = (const float*)d_in[16];
    const float* outproj_w = (const float*)d_in[17];
    const float* normf_w   = (const float*)d_in[18];
    const float* normf_b   = (const float*)d_in[19];
    float* out = (float*)d_out;

    const int M = BATCH * LTOK;  // 8192

    float *p_h, *p_u, *p_xz, *p_y, *p_patch;
    cudaGetSymbolAddress((void**)&p_h, g_h);
    cudaGetSymbolAddress((void**)&p_u, g_u);
    cudaGetSymbolAddress((void**)&p_xz, g_xz);
    cudaGetSymbolAddress((void**)&p_y, g_y);
    cudaGetSymbolAddress((void**)&p_patch, g_patch);

    cudaFuncSetAttribute(gemm_tf32_kernel,
                         cudaFuncAttributeMaxDynamicSharedMemorySize, GEMM_SMEM);

    // 1) patchify + patch embed GEMM + pos embed
    patchify_kernel<<<(M * 64) / 256, 256>>>(x);
    {
        dim3 grid(DIM / 64, M / 128);
        gemm_tf32_kernel<<<grid, 256, GEMM_SMEM>>>(p_patch, patch_w, p_h, nullptr,
                                                   M, DIM, 64, /*wNK=*/0);
    }
    pos_kernel<<<M, DIM>>>(range_res, angle_res, vel_res, hv, patch_b);

    // 2) mamba layers
    for (int l = 0; l < DEPTH; l++) {
        ln4_kernel<<<M / 8, 256>>>(p_h, ln_w + l * DIM, ln_b + l * DIM, p_u);
        {
            dim3 grid((2 * DIM) / 64, M / 128);
            gemm_tf32_kernel<<<grid, 256, GEMM_SMEM>>>(p_u, in_proj_w + (size_t)l * 2 * DIM * DIM,
                                                       p_xz, nullptr,
                                                       M, 2 * DIM, DIM, /*wNK=*/1);
        }
        prep_kernel<<<M, DIM>>>(conv_w + l * DIM * 4, conv_b + l * DIM,
                                xproj_w + (size_t)l * 48 * DIM,
                                dtproj_w + (size_t)l * DIM * DTR,
                                dtproj_b + l * DIM);
        scan1_kernel<<<BATCH * NCH, DIM>>>(A_log + (size_t)l * DIM * NST);
        scan2_kernel<<<(BATCH * DIM * NST) / 256, 256>>>(A_log + (size_t)l * DIM * NST);
        scan3_kernel<<<BATCH * NCH, DIM>>>(A_log + (size_t)l * DIM * NST, D_skip + l * DIM);
        {
            dim3 grid(DIM / 64, M / 128);
            gemm_tf32_kernel<<<grid, 256, GEMM_SMEM>>>(p_y, outproj_w + (size_t)l * DIM * DIM,
                                                       p_h, p_h,
                                                       M, DIM, DIM, /*wNK=*/1);
        }
    }

    // 3) final layernorm -> output
    ln4_kernel<<<M / 8, 256>>>(p_h, normf_w, normf_b, out);
}